// round 14
// baseline (speedup 1.0000x reference)
#include <cuda_runtime.h>
#include <math.h>

#define N_PTS 16384      // 128*128 spatial points
#define N_CH  512        // channels
#define NB    512        // persistent blocks (co-resident: 4/SM x 148 = 592 >= 512)
#define NT    256
#define THRV  0.01f

// ---------------- device state ----------------
__device__ float    g_invnorm[N_PTS];
__device__ float    g_cn[2 * N_CH];             // normalized centers
__device__ float    g_centers[2 * N_CH];        // raw new centers
__device__ float    g_sums[2 * N_CH];           // per-class channel sums
__device__ float    g_cout[2 * N_CH];           // accumulated centers over batches
__device__ float2   g_d[N_PTS];                 // state d2c
__device__ int      g_lab[N_PTS];               // state labels
__device__ unsigned g_labbits[NB];              // packed labels (1 word per block)
__device__ float    g_gpart[NB * 2 * N_CH];     // per-block per-class channel sums (2MB)
__device__ float2   g_dsnap[4 * N_PTS];         // per-batch snapshot of d
__device__ float    g_mn[8], g_mx[8];           // per (b,k) min/max of d
__device__ float    g_cd, g_cini;
__device__ int      g_Ci, g_stable, g_nchanged, g_cnt1;
__device__ unsigned g_done;                     // phase-B last-block counter
__device__ unsigned g_bar_cnt, g_bar_rel;       // grid barrier (monotonic epochs)

// ---------------- the persistent kernel ----------------
__global__ void __launch_bounds__(NT, 4)
k_persist(const float4* __restrict__ F4, const float* __restrict__ CI,
          float* __restrict__ out) {
    const int t = threadIdx.x, b = blockIdx.x;
    __shared__ unsigned s_ep;
    __shared__ float    scn[2 * N_CH];           // 4KB
    __shared__ float4   ws0[8][8], ws1[8][8], wsn[8][8];  // 3KB
    __shared__ float    smr[8][4];
    __shared__ float    sbro[2];
    __shared__ unsigned sLabm;
    __shared__ int      s_active, s_stable;
    __shared__ int      s_is_last;

    // grid barrier: epoch-continuation (state persists across launches safely)
    auto gbar = [&]() {
        __syncthreads();
        if (t == 0) {
            __threadfence();
            unsigned e = ++s_ep;
            unsigned a = atomicAdd(&g_bar_cnt, 1u) + 1u;
            if (a == (unsigned)NB * e) {
                __threadfence();
                atomicExch(&g_bar_rel, e);
            } else {
                while (*((volatile unsigned*)&g_bar_rel) < e) __nanosleep(64);
            }
            __threadfence();
        }
        __syncthreads();
    };

    if (t == 0) s_ep = *((volatile unsigned*)&g_bar_rel);   // stable: no writer yet

    // ---- init: block 0 normalizes centerInit + resets scalars ----
    if (b == 0) {
        float v0a = CI[t],        v0b = CI[t + 256];
        float v1a = CI[N_CH + t], v1b = CI[N_CH + t + 256];
        float r0 = v0a * v0a + v0b * v0b;
        float r1 = v1a * v1a + v1b * v1b;
        for (int off = 16; off; off >>= 1) {
            r0 += __shfl_down_sync(0xffffffffu, r0, off);
            r1 += __shfl_down_sync(0xffffffffu, r1, off);
        }
        if ((t & 31) == 0) { smr[t >> 5][0] = r0; smr[t >> 5][1] = r1; }
        __syncthreads();
        if (t == 0) {
            float a0 = 0.f, a1 = 0.f;
            for (int i = 0; i < 8; i++) { a0 += smr[i][0]; a1 += smr[i][1]; }
            sbro[0] = fmaxf(sqrtf(a0), 1e-12f);
            sbro[1] = fmaxf(sqrtf(a1), 1e-12f);
            *((volatile float*)&g_cd) = 0.f;  *((volatile float*)&g_cini) = 0.f;
            *((volatile int*)&g_Ci) = 0;      *((volatile int*)&g_stable) = 0;
            *((volatile int*)&g_nchanged) = 0; *((volatile int*)&g_cnt1) = 0;
            atomicExch(&g_done, 0u);
        }
        __syncthreads();
        float n0 = sbro[0], n1 = sbro[1];
        __stcg(&g_cn[t],            v0a / n0); __stcg(&g_cn[t + 256],        v0b / n0);
        __stcg(&g_cn[N_CH + t],     v1a / n1); __stcg(&g_cn[N_CH + t + 256], v1b / n1);
        __stcg(&g_cout[t], 0.f); __stcg(&g_cout[t + 256], 0.f);
        __stcg(&g_cout[N_CH + t], 0.f); __stcg(&g_cout[N_CH + t + 256], 0.f);
    }
    gbar();

    const int col = t & 7, chg = t >> 3;
    const float4* Fb = F4 + (b << 3) + col;    // this block's float4 column base

    // ---- 17 steps: s=0 unconditional, s=1..16 masked ----
    for (int s = 0; s < 17; s++) {
        if (t == 0) {
            float cd = __ldcg(&g_cd);
            int ci   = *((volatile int*)&g_Ci);
            s_active = (s == 0) || (cd >= THRV && ci <= 3);
            s_stable = *((volatile int*)&g_stable);
        }
        __syncthreads();

        if (s_active && !s_stable) {
            // ---------- Phase A: one 32MB pass = dots + labels + class sums ----------
#pragma unroll
            for (int i = 0; i < 4; i++) scn[t + 256 * i] = __ldcg(&g_cn[t + 256 * i]);
            __syncthreads();
            float4 a0 = make_float4(0.f, 0.f, 0.f, 0.f);
            float4 a1 = make_float4(0.f, 0.f, 0.f, 0.f);
            float4 ns = make_float4(0.f, 0.f, 0.f, 0.f);
            if (s == 0) {
#pragma unroll
                for (int i = 0; i < 16; i++) {
                    int ch = chg + (i << 5);
                    float4 f = Fb[ch << 12];
                    float w0 = scn[ch], w1 = scn[N_CH + ch];
                    a0.x += f.x * w0; a0.y += f.y * w0; a0.z += f.z * w0; a0.w += f.w * w0;
                    a1.x += f.x * w1; a1.y += f.y * w1; a1.z += f.z * w1; a1.w += f.w * w1;
                    ns.x += f.x * f.x; ns.y += f.y * f.y; ns.z += f.z * f.z; ns.w += f.w * f.w;
                }
            } else {
#pragma unroll
                for (int i = 0; i < 16; i++) {
                    int ch = chg + (i << 5);
                    float4 f = Fb[ch << 12];
                    float w0 = scn[ch], w1 = scn[N_CH + ch];
                    a0.x += f.x * w0; a0.y += f.y * w0; a0.z += f.z * w0; a0.w += f.w * w0;
                    a1.x += f.x * w1; a1.y += f.y * w1; a1.z += f.z * w1; a1.w += f.w * w1;
                }
            }
#pragma unroll
            for (int off = 8; off <= 16; off <<= 1) {
                a0.x += __shfl_xor_sync(0xffffffffu, a0.x, off);
                a0.y += __shfl_xor_sync(0xffffffffu, a0.y, off);
                a0.z += __shfl_xor_sync(0xffffffffu, a0.z, off);
                a0.w += __shfl_xor_sync(0xffffffffu, a0.w, off);
                a1.x += __shfl_xor_sync(0xffffffffu, a1.x, off);
                a1.y += __shfl_xor_sync(0xffffffffu, a1.y, off);
                a1.z += __shfl_xor_sync(0xffffffffu, a1.z, off);
                a1.w += __shfl_xor_sync(0xffffffffu, a1.w, off);
                if (s == 0) {
                    ns.x += __shfl_xor_sync(0xffffffffu, ns.x, off);
                    ns.y += __shfl_xor_sync(0xffffffffu, ns.y, off);
                    ns.z += __shfl_xor_sync(0xffffffffu, ns.z, off);
                    ns.w += __shfl_xor_sync(0xffffffffu, ns.w, off);
                }
            }
            int w = t >> 5;
            if ((t & 31) < 8) { ws0[w][t & 31] = a0; ws1[w][t & 31] = a1; wsn[w][t & 31] = ns; }
            __syncthreads();
            if (t < 32) {
                float d0 = 0.f, d1 = 0.f, nsq = 0.f;
#pragma unroll
                for (int ww = 0; ww < 8; ww++) {
                    d0  += ((const float*)ws0[ww])[t];
                    d1  += ((const float*)ws1[ww])[t];
                    nsq += ((const float*)wsn[ww])[t];
                }
                int n = (b << 5) + t;
                float inv;
                if (s == 0) { inv = 1.f / fmaxf(sqrtf(nsq), 1e-12f); __stcg(&g_invnorm[n], inv); }
                else        { inv = __ldcg(&g_invnorm[n]); }
                float dd0 = 0.5f * (1.f - inv * d0);
                float dd1 = 0.5f * (1.f - inv * d1);
                int lab = (dd1 < dd0) ? 1 : 0;     // argmin; ties -> 0 (jnp.argmin)
                __stcg(&g_d[n], make_float2(dd0, dd1));
                __stcg(&g_lab[n], lab);
                unsigned m = __ballot_sync(0xffffffffu, lab);
                if (t == 0) {
                    sLabm = m;
                    unsigned old = __ldcg(&g_labbits[b]);
                    __stcg(&g_labbits[b], m);
                    if (s > 0) { unsigned x = m ^ old; if (x) atomicAdd(&g_nchanged, (int)__popc(x)); }
                    if (m) atomicAdd(&g_cnt1, (int)__popc(m));
                }
            }
            __syncthreads();
            // sweep 2: same 64KB (L1/L2-hot) -> per-block per-class channel sums
            unsigned mybits = (sLabm >> (col * 4)) & 0xFu;
#pragma unroll
            for (int i = 0; i < 16; i++) {
                int ch = chg + (i << 5);
                float4 f = Fb[ch << 12];
                float s0v = 0.f, s1v = 0.f;
                if (mybits & 1u) s1v += f.x; else s0v += f.x;
                if (mybits & 2u) s1v += f.y; else s0v += f.y;
                if (mybits & 4u) s1v += f.z; else s0v += f.z;
                if (mybits & 8u) s1v += f.w; else s0v += f.w;
#pragma unroll
                for (int dstep = 4; dstep; dstep >>= 1) {
                    s0v += __shfl_down_sync(0xffffffffu, s0v, dstep, 8);
                    s1v += __shfl_down_sync(0xffffffffu, s1v, dstep, 8);
                }
                if (col == 0) {
                    __stcg(&g_gpart[((b << 1) + 0) * N_CH + ch], s0v);
                    __stcg(&g_gpart[((b << 1) + 1) * N_CH + ch], s1v);
                }
            }
            gbar();

            // ---------- Phase B: per-channel reduction + last-block update ----------
            {
                int c = b;
                float s0 = __ldcg(&g_gpart[((t << 1) + 0) * N_CH + c])
                         + __ldcg(&g_gpart[(((t + 256) << 1) + 0) * N_CH + c]);
                float s1 = __ldcg(&g_gpart[((t << 1) + 1) * N_CH + c])
                         + __ldcg(&g_gpart[(((t + 256) << 1) + 1) * N_CH + c]);
                for (int off = 16; off; off >>= 1) {
                    s0 += __shfl_down_sync(0xffffffffu, s0, off);
                    s1 += __shfl_down_sync(0xffffffffu, s1, off);
                }
                if ((t & 31) == 0) { smr[t >> 5][0] = s0; smr[t >> 5][1] = s1; }
                __syncthreads();
                if (t == 0) {
                    float z0 = 0.f, z1 = 0.f;
                    for (int i = 0; i < 8; i++) { z0 += smr[i][0]; z1 += smr[i][1]; }
                    __stcg(&g_sums[c], z0);
                    __stcg(&g_sums[N_CH + c], z1);
                    __threadfence();
                    unsigned a = atomicAdd(&g_done, 1u) + 1u;
                    s_is_last = (a == (unsigned)NB);
                }
                __syncthreads();
                if (s_is_last) {
                    __threadfence();
                    int c1 = *((volatile int*)&g_cnt1);
                    int c0 = N_PTS - c1;
                    float inv0 = 1.f / (float)(c0 + 1), inv1 = 1.f / (float)(c1 + 1);
                    int ca = t, cb2 = t + 256;
                    float s0a = __ldcg(&g_sums[ca]),        s0b = __ldcg(&g_sums[cb2]);
                    float s1a = __ldcg(&g_sums[N_CH + ca]), s1b = __ldcg(&g_sums[N_CH + cb2]);
                    float nc0a = s0a * inv0, nc0b = s0b * inv0;
                    float nc1a = s1a * inv1, nc1b = s1b * inv1;
                    float o0a = __ldcg(&g_cn[ca]),        o0b = __ldcg(&g_cn[cb2]);
                    float o1a = __ldcg(&g_cn[N_CH + ca]), o1b = __ldcg(&g_cn[N_CH + cb2]);
                    __stcg(&g_centers[ca], nc0a);        __stcg(&g_centers[cb2], nc0b);
                    __stcg(&g_centers[N_CH + ca], nc1a); __stcg(&g_centers[N_CH + cb2], nc1b);
                    float r0 = nc0a * nc0a + nc0b * nc0b;
                    float r1 = nc1a * nc1a + nc1b * nc1b;
                    float r2 = nc0a * o0a + nc0b * o0b;
                    float r3 = nc1a * o1a + nc1b * o1b;
                    for (int off = 16; off; off >>= 1) {
                        r0 += __shfl_down_sync(0xffffffffu, r0, off);
                        r1 += __shfl_down_sync(0xffffffffu, r1, off);
                        r2 += __shfl_down_sync(0xffffffffu, r2, off);
                        r3 += __shfl_down_sync(0xffffffffu, r3, off);
                    }
                    if ((t & 31) == 0) { smr[t >> 5][0] = r0; smr[t >> 5][1] = r1; smr[t >> 5][2] = r2; smr[t >> 5][3] = r3; }
                    __syncthreads();
                    if (t == 0) {
                        float b0 = 0.f, b1 = 0.f, b2 = 0.f, b3 = 0.f;
                        for (int i = 0; i < 8; i++) { b0 += smr[i][0]; b1 += smr[i][1]; b2 += smr[i][2]; b3 += smr[i][3]; }
                        float nn0 = fmaxf(sqrtf(b0), 1e-12f);
                        float nn1 = fmaxf(sqrtf(b1), 1e-12f);
                        float cd = 0.5f * (b2 / nn0 + b3 / nn1);
                        int ci = *((volatile int*)&g_Ci);
                        if (ci == 0) *((volatile float*)&g_cini) = *((volatile float*)&g_cini) + cd;
                        *((volatile int*)&g_Ci) = ci + 1;
                        *((volatile float*)&g_cd) = cd;
                        int nch = *((volatile int*)&g_nchanged);
                        if (s > 0 && nch == 0) *((volatile int*)&g_stable) = 1;
                        *((volatile int*)&g_nchanged) = 0;
                        *((volatile int*)&g_cnt1) = 0;
                        atomicExch(&g_done, 0u);
                        sbro[0] = nn0; sbro[1] = nn1;
                    }
                    __syncthreads();
                    float in0 = 1.f / sbro[0], in1 = 1.f / sbro[1];
                    __stcg(&g_cn[ca], nc0a * in0);        __stcg(&g_cn[cb2], nc0b * in0);
                    __stcg(&g_cn[N_CH + ca], nc1a * in1); __stcg(&g_cn[N_CH + cb2], nc1b * in1);
                }
            }
            gbar();
        } else {
            // stable: bookkeeping only; inactive: nothing
            if (s_active && s_stable && b == 0 && t == 0) {
                int ci = *((volatile int*)&g_Ci);
                if (ci == 0) {
                    float cd = *((volatile float*)&g_cd);
                    *((volatile float*)&g_cini) = *((volatile float*)&g_cini) + cd;
                }
                *((volatile int*)&g_Ci) = ci + 1;
            }
            gbar();
        }

        // ---------- batch snapshot ----------
        if (s > 0 && (s & 3) == 0) {
            int bb = (s >> 2) - 1;
            if (b < 64) {
                int n = (b << 8) + t;
                int lab = __ldcg(&g_lab[n]);
                float2 dv = __ldcg(&g_d[n]);
                __stcg(&g_dsnap[(bb << 14) + n], dv);
                __stcg(&out[1024 + (bb << 14) + n], (float)lab);
                int ohb = 66560 + (((bb << 14) + n) << 1);
                __stcg(&out[ohb],     lab ? 0.f : 1.f);
                __stcg(&out[ohb + 1], lab ? 1.f : 0.f);
            } else if (b == 64) {
                for (int i = t; i < 2 * N_CH; i += NT) {
                    float v = __ldcg(&g_cout[i]) + __ldcg(&g_centers[i]);
                    __stcg(&g_cout[i], v);
                }
                if (t == 0) *((volatile int*)&g_Ci) = 0;   // batch boundary reset
            }
            gbar();
        }
    }

    // ---------- per-(batch,class) min/max ----------
    if (b < 8) {
        int bb = b >> 1, k = b & 1;
        float mn = 3.4e38f, mx = -3.4e38f;
        for (int i = t; i < N_PTS; i += NT) {
            float2 dv = __ldcg(&g_dsnap[(bb << 14) + i]);
            float v = k ? dv.y : dv.x;
            mn = fminf(mn, v); mx = fmaxf(mx, v);
        }
        for (int off = 16; off; off >>= 1) {
            mn = fminf(mn, __shfl_down_sync(0xffffffffu, mn, off));
            mx = fmaxf(mx, __shfl_down_sync(0xffffffffu, mx, off));
        }
        if ((t & 31) == 0) { smr[t >> 5][0] = mn; smr[t >> 5][1] = mx; }
        __syncthreads();
        if (t == 0) {
            for (int i = 1; i < 8; i++) { mn = fminf(mn, smr[i][0]); mx = fmaxf(mx, smr[i][1]); }
            __stcg(&g_mn[b], mn); __stcg(&g_mx[b], mx);
        }
    }
    gbar();

    // ---------- final: weight, centers-out, cinidist ----------
    if (b < 256) {
        int idx = (b << 8) + t;
        int bb = idx >> 14;
        int lab = (int)__ldcg(&out[1024 + idx]);
        float2 dv = __ldcg(&g_dsnap[idx]);
        float d = lab ? dv.y : dv.x;
        float rng = __ldcg(&g_mx[bb * 2 + lab]) - __ldcg(&g_mn[bb * 2 + lab]) + 1e-7f;
        __stcg(&out[197632 + idx], 1.1f + d / rng);
        if (idx < 2 * N_CH) __stcg(&out[idx], __ldcg(&g_cout[idx]) * 0.25f);
        if (idx == 0) __stcg(&out[263168], __ldcg(&g_cini) * 0.25f);
    }
}

// ---------------- launch ----------------
extern "C" void kernel_launch(void* const* d_in, const int* in_sizes, int n_in,
                              void* d_out, int out_size) {
    const float* F  = (const float*)d_in[0];   // FeatureT [4,512,128,128]
    const float* CI = (const float*)d_in[1];   // centerInit [2,512]
    if (n_in >= 2 && in_sizes[0] < in_sizes[1]) {
        const float* tmp = F; F = CI; CI = tmp;
    }
    float* out = (float*)d_out;
    (void)out_size;
    k_persist<<<NB, NT>>>((const float4*)F, CI, out);
}

// round 15
// speedup vs baseline: 1.3004x; 1.3004x over previous
#include <cuda_runtime.h>
#include <math.h>

// Problem constants
#define N_PTS 16384      // 128*128 spatial points
#define N_CH  512        // channels
#define NBATCH 4
#define THRV  0.01f
#define THRESH_INC 1536  // max label flips handled by incremental sums
#define NSEG 32          // c-splits in dots kernel (16 channels each)

// ---------------- device state ----------------
__device__ float    g_invnorm[N_PTS];
__device__ float    g_nsqpart[NSEG * N_PTS];      // 2MB
__device__ float    g_dotpart[NSEG * 2 * N_PTS];  // 4MB [p][k][n]
__device__ float    g_cn[2 * N_CH];               // normalized centers
__device__ float    g_centers[2 * N_CH];          // raw new centers
__device__ float    g_sums[2 * N_CH];             // combined per-class channel sums
__device__ float    g_sumpart[4][2][N_CH];        // per-segment partial sums
__device__ float    g_cout[2 * N_CH];             // accumulated centers over batches
__device__ float2   g_d[N_PTS];                   // state d2c
__device__ int      g_lab[N_PTS];                 // state labels
__device__ unsigned g_labbits[N_PTS / 32];        // packed labels (512 words)
__device__ unsigned g_chgbits[N_PTS / 32];        // packed label flips this step
__device__ float2   g_dsnap[NBATCH * N_PTS];      // per-batch snapshot of d
__device__ float    g_mn[8], g_mx[8];             // per (b,k) min/max of d
__device__ float    g_cd;
__device__ float    g_cini;
__device__ int      g_Ci;
__device__ int      g_stable;                     // bitwise fixed point reached
__device__ int      g_nchanged;                   // label flips this step
__device__ int      g_cnt_accum;                  // label-1 count this step
__device__ unsigned g_done;                       // last-block-done counter

__device__ __forceinline__ bool step_active(int first) {
    return first || (g_cd >= THRV && g_Ci <= 3);
}

// ---------------- init scalars + normalize centerInit ----------------
__global__ void k_init(const float* __restrict__ CI) {
    int t = threadIdx.x;   // 512
    float v0 = CI[t], v1 = CI[N_CH + t];
    float r0 = v0 * v0, r1 = v1 * v1;
    __shared__ float sm[16][2];
    for (int off = 16; off; off >>= 1) {
        r0 += __shfl_down_sync(0xffffffffu, r0, off);
        r1 += __shfl_down_sync(0xffffffffu, r1, off);
    }
    if ((t & 31) == 0) { sm[t >> 5][0] = r0; sm[t >> 5][1] = r1; }
    __syncthreads();
    __shared__ float nrm[2];
    if (t == 0) {
        float a0 = 0.f, a1 = 0.f;
        for (int i = 0; i < 16; i++) { a0 += sm[i][0]; a1 += sm[i][1]; }
        nrm[0] = fmaxf(sqrtf(a0), 1e-12f);
        nrm[1] = fmaxf(sqrtf(a1), 1e-12f);
        g_cd = 0.f; g_cini = 0.f; g_Ci = 0;
        g_stable = 0; g_nchanged = 0; g_cnt_accum = 0; g_done = 0u;
    }
    __syncthreads();
    g_cn[t] = v0 / nrm[0];
    g_cn[N_CH + t] = v1 / nrm[1];
    g_cout[t] = 0.f; g_cout[N_CH + t] = 0.f;
}

// ---------------- per-step kernel 1: partial dot products (+ nsq on first) -------
// grid (16 n-blocks, 32 c-splits) = 512 blocks, 256 threads; thread: 1 float4 x 16 ch
__global__ void k_dots(const float4* __restrict__ F4, int first) {
    if (!step_active(first) || g_stable) return;
    __shared__ float scn0[16], scn1[16];
    int ci = blockIdx.y;
    int cb = ci * 16;
    int t = threadIdx.x;
    if (t < 16) { scn0[t] = g_cn[cb + t]; scn1[t] = g_cn[N_CH + cb + t]; }
    __syncthreads();
    int nq = blockIdx.x * 256 + t;             // float4 index over n (4096 total)
    float4 a0 = make_float4(0.f, 0.f, 0.f, 0.f);
    float4 a1 = make_float4(0.f, 0.f, 0.f, 0.f);
    int base = cb * 4096 + nq;
    if (first) {
        float4 ns = make_float4(0.f, 0.f, 0.f, 0.f);
#pragma unroll
        for (int c = 0; c < 16; c++) {
            float4 f = F4[base + c * 4096];
            float w0 = scn0[c], w1 = scn1[c];
            a0.x += f.x * w0; a0.y += f.y * w0; a0.z += f.z * w0; a0.w += f.w * w0;
            a1.x += f.x * w1; a1.y += f.y * w1; a1.z += f.z * w1; a1.w += f.w * w1;
            ns.x += f.x * f.x; ns.y += f.y * f.y; ns.z += f.z * f.z; ns.w += f.w * f.w;
        }
        ((float4*)g_nsqpart)[ci * 4096 + nq] = ns;
    } else {
#pragma unroll
        for (int c = 0; c < 16; c++) {
            float4 f = F4[base + c * 4096];
            float w0 = scn0[c], w1 = scn1[c];
            a0.x += f.x * w0; a0.y += f.y * w0; a0.z += f.z * w0; a0.w += f.w * w0;
            a1.x += f.x * w1; a1.y += f.y * w1; a1.z += f.z * w1; a1.w += f.w * w1;
        }
    }
    ((float4*)g_dotpart)[(ci * 2 + 0) * 4096 + nq] = a0;
    ((float4*)g_dotpart)[(ci * 2 + 1) * 4096 + nq] = a1;
}

// ---------------- per-step kernel 2: labels, flip bits, counts -------------------
__global__ void k_labels(int first) {
    if (!step_active(first) || g_stable) return;
    int t = threadIdx.x;
    int n = blockIdx.x * 256 + t;
    float d0 = 0.f, d1 = 0.f;
#pragma unroll
    for (int p = 0; p < NSEG; p++) {
        d0 += g_dotpart[(p * 2 + 0) * N_PTS + n];
        d1 += g_dotpart[(p * 2 + 1) * N_PTS + n];
    }
    float inv;
    if (first) {
        float s = 0.f;
#pragma unroll
        for (int p = 0; p < NSEG; p++) s += g_nsqpart[p * N_PTS + n];
        inv = 1.f / fmaxf(sqrtf(s), 1e-12f);
        g_invnorm[n] = inv;
    } else {
        inv = g_invnorm[n];
    }
    float dd0 = 0.5f * (1.f - inv * d0);
    float dd1 = 0.5f * (1.f - inv * d1);
    int lab = (dd1 < dd0) ? 1 : 0;             // argmin; ties -> 0 (jnp.argmin)
    g_d[n] = make_float2(dd0, dd1);
    g_lab[n] = lab;
    unsigned m = __ballot_sync(0xffffffffu, lab);
    if ((t & 31) == 0) {
        int w = n >> 5;
        unsigned old = g_labbits[w];
        unsigned x = first ? 0xffffffffu : (m ^ old);  // first step: force full mode
        g_labbits[w] = m;
        g_chgbits[w] = x;
        if (x) atomicAdd(&g_nchanged, __popc(x));
        if (m) atomicAdd(&g_cnt_accum, __popc(m));
    }
}

// ---------------- per-step kernel 3: sums (full/inc/none) + fused update ---------
// grid (512 channels, 4 segments), 256 threads.
// Full mode (first || nch>THRESH): 2048 blocks each sum a 4KB segment of a channel.
// Inc  mode (0<nch<=THRESH): seg==0 blocks (512) apply per-point deltas to g_sums.
// None      (nch==0): block (0,0) goes straight to update; sets stable.
// Last finishing block performs the center update (threadfence+counter).
__global__ void k_sums(const float4* __restrict__ F4, const float* __restrict__ F,
                       int first) {
    if (!step_active(first)) return;
    int c = blockIdx.x, seg = blockIdx.y, t = threadIdx.x;
    if (g_stable) {                                   // bookkeeping only
        if (c == 0 && seg == 0 && t == 0) { if (g_Ci == 0) g_cini += g_cd; g_Ci = g_Ci + 1; }
        return;
    }
    int nch = g_nchanged;
    bool fullMode = (first || nch > THRESH_INC);
    unsigned target;
    __shared__ bool is_last;
    __shared__ unsigned sbits[128];
    __shared__ float smr[8][2];

    if (fullMode) {
        target = 2048u;
        if (t < 128) sbits[t] = g_labbits[seg * 128 + t];
        __syncthreads();
        const float4* row = F4 + c * 4096 + seg * 1024;
        float a0 = 0.f, a1 = 0.f;
#pragma unroll
        for (int j = 0; j < 4; j++) {
            int l4 = t + j * 256;                     // local float4 index 0..1023
            float4 f = row[l4];
            unsigned nib = (sbits[l4 >> 3] >> ((l4 & 7) * 4)) & 15u;
            if (nib & 1u) a1 += f.x; else a0 += f.x;
            if (nib & 2u) a1 += f.y; else a0 += f.y;
            if (nib & 4u) a1 += f.z; else a0 += f.z;
            if (nib & 8u) a1 += f.w; else a0 += f.w;
        }
        for (int off = 16; off; off >>= 1) {
            a0 += __shfl_down_sync(0xffffffffu, a0, off);
            a1 += __shfl_down_sync(0xffffffffu, a1, off);
        }
        if ((t & 31) == 0) { smr[t >> 5][0] = a0; smr[t >> 5][1] = a1; }
        __syncthreads();
        if (t == 0) {
            float s0 = 0.f, s1 = 0.f;
            for (int i = 0; i < 8; i++) { s0 += smr[i][0]; s1 += smr[i][1]; }
            g_sumpart[seg][0][c] = s0;
            g_sumpart[seg][1][c] = s1;
        }
    } else if (nch > 0) {
        target = 512u;
        if (seg != 0) return;
        const float* row = F + c * N_PTS;
        float d0 = 0.f, d1 = 0.f;
        for (int wi = t; wi < N_PTS / 32; wi += 256) {
            unsigned chg = g_chgbits[wi];
            if (!chg) continue;
            unsigned now = g_labbits[wi];
            do {
                int bb = __ffs(chg) - 1; chg &= chg - 1u;
                float f = row[wi * 32 + bb];
                if ((now >> bb) & 1u) { d1 += f; d0 -= f; }   // 0 -> 1
                else                  { d1 -= f; d0 += f; }   // 1 -> 0
            } while (chg);
        }
        for (int off = 16; off; off >>= 1) {
            d0 += __shfl_down_sync(0xffffffffu, d0, off);
            d1 += __shfl_down_sync(0xffffffffu, d1, off);
        }
        if ((t & 31) == 0) { smr[t >> 5][0] = d0; smr[t >> 5][1] = d1; }
        __syncthreads();
        if (t == 0) {
            float s0 = 0.f, s1 = 0.f;
            for (int i = 0; i < 8; i++) { s0 += smr[i][0]; s1 += smr[i][1]; }
            g_sums[c] += s0;
            g_sums[N_CH + c] += s1;
        }
    } else {
        if (!(c == 0 && seg == 0)) return;
        if (t == 0) is_last = true;
        __syncthreads();
        goto do_update;
    }

    if (t == 0) {
        __threadfence();
        unsigned prev = atomicAdd(&g_done, 1u);
        is_last = (prev == target - 1u);
    }
    __syncthreads();
    if (!is_last) return;
    __threadfence();

do_update:
    {
        int c1 = g_cnt_accum;
        int c0 = N_PTS - c1;
        float inv0 = 1.f / (float)(c0 + 1), inv1 = 1.f / (float)(c1 + 1);
        int ca = t, cb2 = t + 256;
        float s0a, s0b, s1a, s1b;
        if (fullMode) {
            s0a = g_sumpart[0][0][ca] + g_sumpart[1][0][ca] + g_sumpart[2][0][ca] + g_sumpart[3][0][ca];
            s0b = g_sumpart[0][0][cb2] + g_sumpart[1][0][cb2] + g_sumpart[2][0][cb2] + g_sumpart[3][0][cb2];
            s1a = g_sumpart[0][1][ca] + g_sumpart[1][1][ca] + g_sumpart[2][1][ca] + g_sumpart[3][1][ca];
            s1b = g_sumpart[0][1][cb2] + g_sumpart[1][1][cb2] + g_sumpart[2][1][cb2] + g_sumpart[3][1][cb2];
            g_sums[ca] = s0a;        g_sums[cb2] = s0b;
            g_sums[N_CH + ca] = s1a; g_sums[N_CH + cb2] = s1b;
        } else {
            s0a = g_sums[ca]; s0b = g_sums[cb2];
            s1a = g_sums[N_CH + ca]; s1b = g_sums[N_CH + cb2];
        }
        float nc0a = s0a * inv0, nc0b = s0b * inv0;
        float nc1a = s1a * inv1, nc1b = s1b * inv1;
        float o0a = g_cn[ca], o0b = g_cn[cb2];
        float o1a = g_cn[N_CH + ca], o1b = g_cn[N_CH + cb2];
        g_centers[ca] = nc0a;        g_centers[cb2] = nc0b;
        g_centers[N_CH + ca] = nc1a; g_centers[N_CH + cb2] = nc1b;

        float r0 = nc0a * nc0a + nc0b * nc0b;
        float r1 = nc1a * nc1a + nc1b * nc1b;
        float r2 = nc0a * o0a + nc0b * o0b;
        float r3 = nc1a * o1a + nc1b * o1b;
        __shared__ float smu[8][4];
        for (int off = 16; off; off >>= 1) {
            r0 += __shfl_down_sync(0xffffffffu, r0, off);
            r1 += __shfl_down_sync(0xffffffffu, r1, off);
            r2 += __shfl_down_sync(0xffffffffu, r2, off);
            r3 += __shfl_down_sync(0xffffffffu, r3, off);
        }
        if ((t & 31) == 0) { smu[t >> 5][0] = r0; smu[t >> 5][1] = r1; smu[t >> 5][2] = r2; smu[t >> 5][3] = r3; }
        __syncthreads();
        __shared__ float bro[2];
        if (t == 0) {
            float b0 = 0.f, b1 = 0.f, b2 = 0.f, b3 = 0.f;
            for (int i = 0; i < 8; i++) { b0 += smu[i][0]; b1 += smu[i][1]; b2 += smu[i][2]; b3 += smu[i][3]; }
            float nn0 = fmaxf(sqrtf(b0), 1e-12f);
            float nn1 = fmaxf(sqrtf(b1), 1e-12f);
            float cd = 0.5f * (b2 / nn0 + b3 / nn1);
            if (g_Ci == 0) g_cini += cd;
            g_Ci = g_Ci + 1;
            g_cd = cd;
            bro[0] = nn0; bro[1] = nn1;
            if (!first && g_nchanged == 0) g_stable = 1;   // bitwise fixed point
            g_nchanged = 0;
            g_cnt_accum = 0;
            g_done = 0u;
        }
        __syncthreads();
        float in0 = 1.f / bro[0], in1 = 1.f / bro[1];
        g_cn[ca] = nc0a * in0;        g_cn[cb2] = nc0b * in0;
        g_cn[N_CH + ca] = nc1a * in1; g_cn[N_CH + cb2] = nc1b * in1;
    }
}

// ---------------- batch snapshot ----------------
__global__ void k_snapshot(int b, float* __restrict__ out) {
    int t = threadIdx.x;
    int n = blockIdx.x * 256 + t;
    int lab = g_lab[n];
    g_dsnap[(b << 14) + n] = g_d[n];
    out[1024 + (b << 14) + n] = (float)lab;                    // labels
    int ohb = 66560 + (((b << 14) + n) << 1);                  // one-hot
    out[ohb]     = lab ? 0.f : 1.f;
    out[ohb + 1] = lab ? 1.f : 0.f;
    if (blockIdx.x == 0) {
        for (int i = t; i < 2 * N_CH; i += 256) g_cout[i] += g_centers[i];
        if (t == 0) g_Ci = 0;                                   // batch boundary reset
    }
}

// ---------------- per-(batch,class) min/max of snapshot d ----------------
__global__ void k_minmax() {
    int b = blockIdx.x >> 1, k = blockIdx.x & 1;
    int t = threadIdx.x;
    float mn = 3.4e38f, mx = -3.4e38f;
    for (int i = t; i < N_PTS; i += 256) {
        float2 dv = g_dsnap[(b << 14) + i];
        float v = k ? dv.y : dv.x;
        mn = fminf(mn, v); mx = fmaxf(mx, v);
    }
    __shared__ float smn[8], smx[8];
    for (int off = 16; off; off >>= 1) {
        mn = fminf(mn, __shfl_down_sync(0xffffffffu, mn, off));
        mx = fmaxf(mx, __shfl_down_sync(0xffffffffu, mx, off));
    }
    if ((t & 31) == 0) { smn[t >> 5] = mn; smx[t >> 5] = mx; }
    __syncthreads();
    if (t == 0) {
        for (int i = 1; i < 8; i++) { mn = fminf(mn, smn[i]); mx = fmaxf(mx, smx[i]); }
        g_mn[blockIdx.x] = mn; g_mx[blockIdx.x] = mx;
    }
}

// ---------------- final: weight, centers-out, cinidist ----------------
__global__ void k_final(float* __restrict__ out) {
    int idx = blockIdx.x * 256 + threadIdx.x;   // 65536 = 4*16384
    int b = idx >> 14;
    int lab = (int)out[1024 + idx];
    float2 dv = g_dsnap[idx];
    float d = lab ? dv.y : dv.x;
    float rng = g_mx[b * 2 + lab] - g_mn[b * 2 + lab] + 1e-7f;
    out[197632 + idx] = 1.1f + d / rng;         // weight = (1 - (-d/rng)) + 0.1
    if (idx < 2 * N_CH) out[idx] = g_cout[idx] * 0.25f;        // centersIterout
    if (idx == 0) out[263168] = g_cini * 0.25f;                // cinidist
}

// ---------------- launch ----------------
extern "C" void kernel_launch(void* const* d_in, const int* in_sizes, int n_in,
                              void* d_out, int out_size) {
    const float* F  = (const float*)d_in[0];   // FeatureT [4,512,128,128]
    const float* CI = (const float*)d_in[1];   // centerInit [2,512]
    if (n_in >= 2 && in_sizes[0] < in_sizes[1]) {  // defensive: identify by size
        const float* tmp = F; F = CI; CI = tmp;
    }
    float* out = (float*)d_out;
    (void)out_size;

    k_init<<<1, 512>>>(CI);

    // 17 steps: s=0 unconditional (centersIter is None), s=1..16 masked (4 per batch)
    for (int s = 0; s < 17; s++) {
        int first = (s == 0) ? 1 : 0;
        k_dots<<<dim3(16, NSEG), 256>>>((const float4*)F, first);
        k_labels<<<64, 256>>>(first);
        k_sums<<<dim3(512, 4), 256>>>((const float4*)F, F, first);
        if (s > 0 && (s & 3) == 0) {
            k_snapshot<<<64, 256>>>(s / 4 - 1, out);
        }
    }

    k_minmax<<<8, 256>>>();
    k_final<<<256, 256>>>(out);
}